// round 5
// baseline (speedup 1.0000x reference)
#include <cuda_runtime.h>
#include <cuda_bf16.h>

// out[b,s,n,c] = x[b,s,n,c] + pe[n,c],  x: (8,16,1024,256) fp32
// pe[n,2k]   = sin(n / (2000*k/256 + 0.01))
// pe[n,2k+1] = cos(n / (2000*k/256 + 0.01))
//
// R5: two kernels. (1) build 1MB pe table (cheap, overlapped-ish).
// (2) fine-grained streaming: block = (n, 16 reps), 256 thr, BATCH=4
// independent ldcs per thread, pe from L2 table (one load per thread).
// Low regs -> 100% occupancy -> max chip-level MLP + fine drain tail.

#define N_POS 1024
#define D_DIM 256
#define ROW_VEC (D_DIM / 4)        // 64 float4 per row
#define PE_VEC (N_POS * ROW_VEC)   // 65536 float4
#define REPS 128                   // B*S
#define REPS_PER_BLK 16            // gridDim.y = 8
#define BATCH 4

__device__ float4 g_pe[PE_VEC];    // 1 MB table

__global__ void pe_init_kernel() {
    int t = blockIdx.x * blockDim.x + threadIdx.x;   // 0..131071 (n,k) pairs
    int n = t >> 7;                 // 0..1023
    int k = t & 127;                // 0..127
    const float denom = (2000.0f / 256.0f) * (float)k + 0.01f;
    float s, c;
    sincosf((float)n / denom, &s, &c);
    reinterpret_cast<float2*>(g_pe)[t] = make_float2(s, c);
}

__global__ void __launch_bounds__(256) add_pe_stream(const float4* __restrict__ x,
                                                     float4* __restrict__ out) {
    const int n = blockIdx.x;                 // 0..1023
    const int t = threadIdx.x;
    const int lane = t & (ROW_VEC - 1);       // 0..63
    const int rsub = t >> 6;                  // 0..3

    const float4 p = __ldg(&g_pe[n * ROW_VEC + lane]);

    const unsigned rstride = N_POS * ROW_VEC;              // 65536
    const int r0 = blockIdx.y * REPS_PER_BLK + rsub;
    const unsigned b = (unsigned)(r0 * N_POS + n) * ROW_VEC + lane;
    const unsigned bstride = 4u * rstride;

    float4 a0 = __ldcs(&x[b + 0u * bstride]);
    float4 a1 = __ldcs(&x[b + 1u * bstride]);
    float4 a2 = __ldcs(&x[b + 2u * bstride]);
    float4 a3 = __ldcs(&x[b + 3u * bstride]);
    a0.x += p.x; a0.y += p.y; a0.z += p.z; a0.w += p.w;
    a1.x += p.x; a1.y += p.y; a1.z += p.z; a1.w += p.w;
    a2.x += p.x; a2.y += p.y; a2.z += p.z; a2.w += p.w;
    a3.x += p.x; a3.y += p.y; a3.z += p.z; a3.w += p.w;
    __stcs(&out[b + 0u * bstride], a0);
    __stcs(&out[b + 1u * bstride], a1);
    __stcs(&out[b + 2u * bstride], a2);
    __stcs(&out[b + 3u * bstride], a3);
}

extern "C" void kernel_launch(void* const* d_in, const int* in_sizes, int n_in,
                              void* d_out, int out_size) {
    const float4* x = (const float4*)d_in[0];
    float4* out = (float4*)d_out;

    pe_init_kernel<<<(N_POS * 128) / 256, 256>>>();            // 512 blocks
    dim3 grid(N_POS, REPS / REPS_PER_BLK, 1);                  // (1024, 8)
    add_pe_stream<<<grid, 256>>>(x, out);
}